// round 8
// baseline (speedup 1.0000x reference)
#include <cuda_runtime.h>
#include <cuda_bf16.h>

// Problem constants (fixed by the reference)
#define NROWS 8192
#define NCOLS 8192
#define RB 32
#define CB 32
#define HID 100
#define DIO (RB*CB)
#define SPLITS 16                      // row-slots per (rb,cb) block
#define NITEMS (RB*CB*SPLITS)          // 16384 per-warp work items
#define CTAS_PER_SM 4
#define NB_CTAS (148*CTAS_PER_SM)      // 592, all co-resident
#define ROFF  (SPLITS*NCOLS)           // 16-row float offset (constant)
#define ROFF4 (SPLITS*NCOLS/4)         // 16-row float4 offset (constant)

// Scratch (no cudaMalloc allowed)
__device__ float g_blk[RB*CB];
__device__ int   g_rowb[RB+1];
__device__ int   g_colb[CB+1];
__device__ int   g_work;
__device__ unsigned g_bar_arrive = 0;
__device__ volatile unsigned g_bar_gen = 0;

// Generation-based grid barrier: safe across graph replays (state self-resets),
// deadlock-free because all NB_CTAS are co-resident.
__device__ __forceinline__ void grid_barrier() {
    __syncthreads();
    if (threadIdx.x == 0) {
        __threadfence();
        unsigned gen = g_bar_gen;
        unsigned a = atomicAdd(&g_bar_arrive, 1u);
        if (a == NB_CTAS - 1u) {
            atomicExch(&g_bar_arrive, 0u);
            __threadfence();
            g_bar_gen = gen + 1u;
        } else {
            while (g_bar_gen == gen) { }
            __threadfence();
        }
    }
    __syncthreads();
}

__global__ __launch_bounds__(256, CTAS_PER_SM)
void k_fused(const float* __restrict__ X,
             const int* __restrict__ row_ids,
             const int* __restrict__ col_ids,
             const float* __restrict__ W1, const float* __restrict__ b1,
             const float* __restrict__ W2, const float* __restrict__ b2,
             const float* __restrict__ W3, const float* __restrict__ b3,
             float* __restrict__ out) {
    __shared__ int   srow[RB + 1];
    __shared__ int   scol[CB + 1];
    // MLP scratch (CTA 0 only, phase C)
    __shared__ float xs[DIO];
    __shared__ float h1p[800];
    __shared__ float h2p[1000];
    __shared__ float h1[HID];
    __shared__ float h2[HID];

    const int t = threadIdx.x;
    const int lane = t & 31;

    // ---------------- Phase A: setup (distributed) ----------------
    if (blockIdx.x < 32) {
        const bool rowpass = (blockIdx.x < 16);
        const int  slice   = rowpass ? blockIdx.x : (blockIdx.x - 16);
        const int  nb  = rowpass ? RB : CB;
        const int  n   = rowpass ? NROWS : NCOLS;
        const int* ids = rowpass ? row_ids : col_ids;
        int*   bnd = rowpass ? g_rowb : g_colb;
        float* o   = out + DIO + (rowpass ? 0 : (RB + 1));
        const int i = slice * 512 + t * 2;
        #pragma unroll
        for (int d = 0; d < 2; d++) {
            int g = i + d;
            if (g < n) {
                int cur  = ids[g];
                int prev = (g == 0) ? -1 : ids[g - 1];
                for (int k = prev + 1; k <= cur; k++) { bnd[k] = g; o[k] = (float)g; }
                if (g == n - 1)
                    for (int k = cur + 1; k <= nb; k++) { bnd[k] = n; o[k] = (float)n; }
            }
        }
    } else if (blockIdx.x == 32) {
        for (int j = t; j < DIO; j += 256) g_blk[j] = 0.0f;
    } else if (blockIdx.x == 33 && t == 0) {
        g_work = 0;
    }

    grid_barrier();

    // boundary arrays -> smem
    if (t <= RB) srow[t] = g_rowb[t];
    else if (t >= 64 && t <= 64 + CB) scol[t - 64] = g_colb[t - 64];
    __syncthreads();

    // ---------------- Phase B: per-warp dynamic block-sum ----------------
    // Prefetched queue: fetch item i+1 while processing item i.
    int item;
    if (lane == 0) item = atomicAdd(&g_work, 1);
    item = __shfl_sync(0xFFFFFFFFu, item, 0);

    while (item < NITEMS) {
        int next;
        if (lane == 0) next = atomicAdd(&g_work, 1);   // overlaps with work below
        next = __shfl_sync(0xFFFFFFFFu, next, 0);

        const int rb = item >> 9;
        const int cb = (item >> 4) & 31;
        const int ws = item & (SPLITS - 1);
        const int rlo = srow[rb], rhi = srow[rb + 1];
        const int clo = scol[cb], chi = scol[cb + 1];

        // 16B-aligned body [ca, ce), scalar head and tail
        int ca = (clo + 3) & ~3; if (ca > chi) ca = chi;
        int ce = chi & ~3;       if (ce < ca)  ce = ca;
        const int hN = ca - clo, tN = chi - ce;
        const int c4lo = ca >> 2, c4hi = ce >> 2;

        float a0 = 0.f, a1 = 0.f, a2 = 0.f, a3 = 0.f;
        int r = rlo + ws;

        // 4-row groups: rows r, r+16, r+32, r+48 -> ONE base pointer,
        // constant byte offsets (LDG [R+imm]); 2-col x 4-row = 8 LDG in flight.
        for (; r + 3 * SPLITS < rhi; r += 4 * SPLITS) {
            const float*  q = X + (size_t)r * NCOLS;
            const float4* p = (const float4*)q;
            if (lane < hN) {
                int h = clo + lane;
                a0 += q[h];            a1 += q[h + ROFF];
                a2 += q[h + 2*ROFF];   a3 += q[h + 3*ROFF];
            }
            int c = c4lo + lane;
            for (; c + 32 < c4hi; c += 64) {
                float4 v00 = p[c];              float4 v01 = p[c + 32];
                float4 v10 = p[c + ROFF4];      float4 v11 = p[c + 32 + ROFF4];
                float4 v20 = p[c + 2*ROFF4];    float4 v21 = p[c + 32 + 2*ROFF4];
                float4 v30 = p[c + 3*ROFF4];    float4 v31 = p[c + 32 + 3*ROFF4];
                a0 += ((v00.x+v00.y)+(v00.z+v00.w)) + ((v01.x+v01.y)+(v01.z+v01.w));
                a1 += ((v10.x+v10.y)+(v10.z+v10.w)) + ((v11.x+v11.y)+(v11.z+v11.w));
                a2 += ((v20.x+v20.y)+(v20.z+v20.w)) + ((v21.x+v21.y)+(v21.z+v21.w));
                a3 += ((v30.x+v30.y)+(v30.z+v30.w)) + ((v31.x+v31.y)+(v31.z+v31.w));
            }
            if (c < c4hi) {
                float4 v00 = p[c];
                float4 v10 = p[c + ROFF4];
                float4 v20 = p[c + 2*ROFF4];
                float4 v30 = p[c + 3*ROFF4];
                a0 += (v00.x+v00.y)+(v00.z+v00.w);
                a1 += (v10.x+v10.y)+(v10.z+v10.w);
                a2 += (v20.x+v20.y)+(v20.z+v20.w);
                a3 += (v30.x+v30.y)+(v30.z+v30.w);
            }
            if (lane < tN) {
                int e = ce + lane;
                a0 += q[e];            a1 += q[e + ROFF];
                a2 += q[e + 2*ROFF];   a3 += q[e + 3*ROFF];
            }
        }
        // leftover rows (0..3), one at a time
        for (; r < rhi; r += SPLITS) {
            const float*  q = X + (size_t)r * NCOLS;
            const float4* p = (const float4*)q;
            if (lane < hN) a0 += q[clo + lane];
            for (int c = c4lo + lane; c < c4hi; c += 32) {
                float4 v = p[c];
                a0 += (v.x + v.y) + (v.z + v.w);
            }
            if (lane < tN) a0 += q[ce + lane];
        }

        float acc = (a0 + a1) + (a2 + a3);
        #pragma unroll
        for (int o = 16; o; o >>= 1) acc += __shfl_xor_sync(0xFFFFFFFFu, acc, o);
        if (lane == 0) atomicAdd(&g_blk[rb * CB + cb], acc);   // fire-and-forget

        item = next;
    }

    grid_barrier();

    // ---------------- Phase C: MLP (CTA 0 only) ----------------
    if (blockIdx.x != 0) return;

    // block mean (256 threads -> 4 bins each)
    #pragma unroll
    for (int d = 0; d < 4; d++) {
        int b = t + d * 256;
        int rb = b >> 5, cbi = b & 31;
        float rc = (float)(srow[rb + 1] - srow[rb]);
        float cc = (float)(scol[cbi + 1] - scol[cbi]);
        float cnt = fmaxf(rc * cc, 1.0f);
        xs[b] = g_blk[b] / cnt;
    }
    __syncthreads();

    // layer 1: h1 = relu(x @ W1 + b1), x[1024], W1[1024,100]; 8 K-slices x 100
    for (int u = t; u < 800; u += 256) {
        const int j  = u % HID;
        const int i0 = (u / HID) * 128;
        float acc = 0.f;
        #pragma unroll 8
        for (int i = 0; i < 128; i++)
            acc += xs[i0 + i] * W1[(size_t)(i0 + i) * HID + j];
        h1p[u] = acc;
    }
    __syncthreads();
    if (t < HID) {
        float a = b1[t];
        #pragma unroll
        for (int sl = 0; sl < 8; sl++) a += h1p[sl * HID + t];
        h1[t] = fmaxf(a, 0.f);
    }
    __syncthreads();

    // layer 2: h2 = relu(h1 @ W2 + b2), W2[100,100]; 10 K-slices x 100
    for (int u = t; u < 1000; u += 256) {
        const int j  = u % HID;
        const int i0 = (u / HID) * 10;
        float acc = 0.f;
        #pragma unroll
        for (int i = 0; i < 10; i++)
            acc += h1[i0 + i] * W2[(i0 + i) * HID + j];
        h2p[u] = acc;
    }
    __syncthreads();
    if (t < HID) {
        float a = b2[t];
        #pragma unroll
        for (int sl = 0; sl < 10; sl++) a += h2p[sl * HID + t];
        h2[t] = fmaxf(a, 0.f);
    }
    __syncthreads();

    // layer 3: out = sigmoid(h2 @ W3 + b3), W3[100,1024]
    #pragma unroll
    for (int d = 0; d < 4; d++) {
        int j = t + d * 256;
        float a = b3[j];
        #pragma unroll 10
        for (int i = 0; i < HID; i++) a += h2[i] * W3[(size_t)i * DIO + j];
        out[j] = 1.0f / (1.0f + __expf(-a));
    }
}

extern "C" void kernel_launch(void* const* d_in, const int* in_sizes, int n_in,
                              void* d_out, int out_size) {
    const float* X       = (const float*)d_in[0];
    const int*   row_ids = (const int*)  d_in[1];
    const int*   col_ids = (const int*)  d_in[2];
    const float* W1      = (const float*)d_in[3];
    const float* b1      = (const float*)d_in[4];
    const float* W2      = (const float*)d_in[5];
    const float* b2      = (const float*)d_in[6];
    const float* W3      = (const float*)d_in[7];
    const float* b3      = (const float*)d_in[8];
    float* out = (float*)d_out;

    k_fused<<<NB_CTAS, 256>>>(X, row_ids, col_ids, W1, b1, W2, b2, W3, b3, out);
}